// round 16
// baseline (speedup 1.0000x reference)
#include <cuda_runtime.h>
#include <cuda_bf16.h>

// ---------------------------------------------------------------------------
// Quanv3x3 quantum layer — closed-form factorized sim, single kernel,
// warp-split A/B, loads-first overlap, ONE BLOCK PER SM:
// 150 blocks x 384 threads, 192 sims per block (28800 = 150*192 exact).
// Fewer CTAs -> 3x fewer prologues / dispatch slots; 12 warps per SM to
// absorb sync skew. Kernel is launch-ramp dominated; math is ~0.4us.
//
//   z = PB0*(p0-p1) + PB1*[w0*(p0-p1) + w2*Re(t) - w1*Im(t)]
//
// Warp pairs: even warp -> group A (q0..q3) for 32 sims, odd warp -> group
// B (q4..q8) for the same 32 sims. Exchange 6 floats/sim via smem;
// threads 0..191 combine + write. Fast __sincosf (4.4e-7 vs 1e-3 budget).
// ---------------------------------------------------------------------------

struct c2 { float r, i; };

__device__ __forceinline__ float nrm(c2 a) { return a.r * a.r + a.i * a.i; }
// a * conj(b)
__device__ __forceinline__ c2 cprod(c2 a, c2 b) {
    return { a.r * b.r + a.i * b.i, a.i * b.r - a.r * b.i };
}

// Pair state after CRZ(za)+CRX(xb): ctrl qubit (sc,cc), tgt qubit (st,ct),
// both starting as RX-product states u = (s, i*c). Index: X[ctrl][tgt].
__device__ __forceinline__ void build_pair(
    float sc, float cc, float st, float ct,
    float zc, float zs, float xc, float xs,
    c2& X00, c2& X01, c2& X10, c2& X11)
{
    X00 = { sc * st, 0.0f };
    X01 = { 0.0f, sc * ct };
    float y10r =  cc * st * zs, y10i =  cc * st * zc;   // (i*cc*st)*e^{-iza}
    float y11r = -cc * ct * zc, y11i = -cc * ct * zs;   // (-cc*ct)*e^{+iza}
    X10 = { xc * y10r + xs * y11i,  xc * y10i - xs * y11r };
    X11 = { xs * y10i + xc * y11r, -xs * y10r + xc * y11i };
}

// Apply M = RX(xb)*RZ(za) (SU(2): [[al, -conj(be)],[be, conj(al)]]).
__device__ __forceinline__ void mapply(c2 al, c2 be, c2 a, c2 b, c2& o0, c2& o1) {
    o0.r = al.r * a.r - al.i * a.i - be.r * b.r - be.i * b.i;
    o0.i = al.r * a.i + al.i * a.r - be.r * b.i + be.i * b.r;
    o1.r = be.r * a.r - be.i * a.i + al.r * b.r + al.i * b.i;
    o1.i = be.r * a.i + be.i * a.r + al.r * b.i - al.i * b.r;
}

#define KW 33     // smem row stride for constants
#define NSIM 192  // sims per block
#define PIf 3.14159265358979323846f

__global__ __launch_bounds__(384) void fused_kernel(
    const float* __restrict__ x,
    const float* __restrict__ qp,
    float* __restrict__ out)
{
    __shared__ float k[4 * KW];                                   // constants
    __shared__ float sA0[NSIM], sA1[NSIM], sAr[NSIM], sAi[NSIM];  // A results
    __shared__ float sB0[NSIM], sB1[NSIM];                        // B results

    int tid = threadIdx.x;
    int warp = tid >> 5, lane = tid & 31;
    int ls   = (warp >> 1) * 32 + lane;     // local sim 0..191
    int role = warp & 1;                     // 0 = group A, 1 = group B
    int sim  = blockIdx.x * NSIM + ls;

    int ch   = sim & 3;
    int cell = sim >> 2;
    int cc   = cell % 30;
    int rc   = cell / 30;
    int rr   = rc % 30;
    int b    = rc / 30;

    int r_ = min(max(rr - 1, 0), 27);   // clamp; border masked at write
    int c_ = min(max(cc - 1, 0), 27);
    const float* xb = x + (b * 900 + r_ * 30 + c_) * 3;

    // ---- pixel loads FIRST: independent, overlap the prologue -------------
    float px[15];
    if (role == 0) {
#pragma unroll
        for (int j = 0; j < 4; j++) {
            int dr = j / 3, dc = j - dr * 3;
            const float* p = xb + (dr * 30 + dc) * 3;
            px[3 * j + 0] = __ldg(p + 0);
            px[3 * j + 1] = __ldg(p + 1);
            px[3 * j + 2] = __ldg(p + 2);
        }
    } else {
#pragma unroll
        for (int j = 0; j < 5; j++) {
            int q = j + 4;
            int dr = q / 3, dc = q - dr * 3;
            const float* p = xb + (dr * 30 + dc) * 3;
            px[3 * j + 0] = __ldg(p + 0);
            px[3 * j + 1] = __ldg(p + 1);
            px[3 * j + 2] = __ldg(p + 2);
        }
    }

    // ---- single-phase constant build: thread t (<4) does channel t --------
    if (tid < 4) {
        const float* th = qp + tid * 16;
        float s_[16], c_[16];
#pragma unroll
        for (int j = 0; j < 14; j++)
            __sincosf(__ldg(th + j) * 0.5f, &s_[j], &c_[j]);
        float* kk = k + tid * KW;
        kk[0] = c_[0];  kk[1] = s_[0];  kk[2] = c_[1];  kk[3] = s_[1];
        kk[4] = c_[2];  kk[5] = s_[2];  kk[6] = c_[3];  kk[7] = s_[3];
        kk[8]  =  c_[5] * c_[4];  kk[9]  = -c_[5] * s_[4];
        kk[10] = -s_[5] * s_[4];  kk[11] = -s_[5] * c_[4];
        kk[12] = c_[6]; kk[13] = s_[6]; kk[14] = c_[7]; kk[15] = s_[7];
        kk[16] = c_[8]; kk[17] = s_[8]; kk[18] = c_[9]; kk[19] = s_[9];
        kk[20] =  c_[11] * c_[10]; kk[21] = -c_[11] * s_[10];
        kk[22] = -s_[11] * s_[10]; kk[23] = -s_[11] * c_[10];
        kk[24] =  c_[13] * c_[12]; kk[25] = -c_[13] * s_[12];
        kk[26] = -s_[13] * s_[12]; kk[27] = -s_[13] * c_[12];
        float s14, c14, s15, c15;
        __sincosf(__ldg(th + 14), &s14, &c14);
        __sincosf(__ldg(th + 15), &s15, &c15);
        kk[28] = c15;
        kk[29] = 2.0f * s15 * c14;
        kk[30] = 2.0f * s15 * s14;
    }
    __syncthreads();

    const float* kk = k + ch * KW;

    if (role == 0) {
        // ---- group A: pixels/qubits 0..3 ----------------------------------
        float ps[4], pc_[4];
#pragma unroll
        for (int j = 0; j < 4; j++) {
            float a = (px[3 * j] + px[3 * j + 1] + px[3 * j + 2]) * (1.0f / 3.0f);
            __sincosf(PIf * a, &ps[j], &pc_[j]);
        }
        c2 S00, S01, S10, S11;
        build_pair(ps[1], pc_[1], ps[0], pc_[0],
                   kk[0], kk[1], kk[2], kk[3], S00, S01, S10, S11);
        c2 T00, T01, T10, T11;
        build_pair(ps[3], pc_[3], ps[2], pc_[2],
                   kk[4], kk[5], kk[6], kk[7], T00, T01, T10, T11);
        c2 a2 = { kk[8], kk[9] };
        c2 b2 = { kk[10], kk[11] };
        c2 P00, P01, P10, P11;
        mapply(a2, b2, S00, S01, P00, P01);
        mapply(a2, b2, S10, S11, P10, P11);

        float T0n = nrm(T00) + nrm(T10);
        float T1n = nrm(T01) + nrm(T11);
        float n0S = nrm(S00) + nrm(S10);
        float n1S = nrm(S01) + nrm(S11);
        c2 tS; { c2 u = cprod(S00, S01), v = cprod(S10, S11); tS = { u.r + v.r, u.i + v.i }; }
        float n0P = nrm(P00) + nrm(P10);
        float n1P = nrm(P01) + nrm(P11);
        c2 tP; { c2 u = cprod(P00, P01), v = cprod(P10, P11); tP = { u.r + v.r, u.i + v.i }; }

        sA0[ls] = T0n * n0S + T1n * n0P;
        sA1[ls] = T0n * n1S + T1n * n1P;
        sAr[ls] = T0n * tS.r + T1n * tP.r;
        sAi[ls] = T0n * tS.i + T1n * tP.i;
    } else {
        // ---- group B: pixels/qubits 4..8 ----------------------------------
        float ps[5], pc_[5];
#pragma unroll
        for (int j = 0; j < 5; j++) {
            float a = (px[3 * j] + px[3 * j + 1] + px[3 * j + 2]) * (1.0f / 3.0f);
            __sincosf(PIf * a, &ps[j], &pc_[j]);
        }
        // ps[0]=q4, ps[1]=q5, ps[2]=q6, ps[3]=q7, ps[4]=q8
        c2 C00, C01, C10, C11;
        build_pair(ps[4], pc_[4], ps[3], pc_[3],
                   kk[12], kk[13], kk[14], kk[15], C00, C01, C10, C11);
        c2 D00, D01, D10, D11;
        build_pair(ps[1], pc_[1], ps[0], pc_[0],
                   kk[16], kk[17], kk[18], kk[19], D00, D01, D10, D11);
        float Cn0 = nrm(C00) + nrm(C10);
        float Cn1 = nrm(C01) + nrm(C11);

        c2 a5 = { kk[20], kk[21] };
        c2 b5 = { kk[22], kk[23] };
        c2 u60 = { ps[2], 0.0f }, u61 = { 0.0f, pc_[2] };
        c2 v60, v61;
        mapply(a5, b5, u60, u61, v60, v61);
        float wn00 = ps[2] * ps[2], wn01 = pc_[2] * pc_[2];
        float wn10 = nrm(v60), wn11 = nrm(v61);

        c2 a6 = { kk[24], kk[25] };
        c2 b6 = { kk[26], kk[27] };
        c2 E00, E01, E10, E11;
        mapply(a6, b6, D00, D01, E00, E01);
        mapply(a6, b6, D10, D11, E10, E11);

        float DnD0 = nrm(D00) + nrm(D10);
        float DnD1 = nrm(D01) + nrm(D11);
        float Dn60 = nrm(E00) + nrm(E10);
        float Dn61 = nrm(E01) + nrm(E11);

        sB0[ls] = Cn0 * (wn00 * DnD0 + wn01 * Dn60) +
                  Cn1 * (wn10 * DnD0 + wn11 * Dn60);
        sB1[ls] = Cn0 * (wn00 * DnD1 + wn01 * Dn61) +
                  Cn1 * (wn10 * DnD1 + wn11 * Dn61);
    }
    __syncthreads();

    // ---- combine + write (threads 0..NSIM-1) ------------------------------
    if (tid < NSIM) {
        int sim2  = blockIdx.x * NSIM + tid;
        int ch2   = sim2 & 3;
        int cell2 = sim2 >> 2;
        int cc2   = cell2 % 30;
        int rc2   = cell2 / 30;
        int rr2   = rc2 % 30;
        const float* kk2 = k + ch2 * KW;

        float dz = sA0[tid] - sA1[tid];
        float z  = sB0[tid] * dz +
                   sB1[tid] * (kk2[28] * dz + kk2[30] * sAr[tid] - kk2[29] * sAi[tid]);
        bool interior = (rr2 >= 1 && rr2 <= 28 && cc2 >= 1 && cc2 <= 28);
        out[sim2] = interior ? (z + 1.0f) * 0.5f : 0.0f;
    }
}

extern "C" void kernel_launch(void* const* d_in, const int* in_sizes, int n_in,
                              void* d_out, int out_size) {
    const float* x  = (const float*)d_in[0];
    const float* qp = (const float*)d_in[1];
    if (n_in >= 2 && in_sizes[0] == 64) {
        const float* tp = x; x = qp; qp = tp;
    }
    float* out = (float*)d_out;

    fused_kernel<<<150, 384>>>(x, qp, out);
}